// round 5
// baseline (speedup 1.0000x reference)
#include <cuda_runtime.h>
#include <cuda_bf16.h>
#include <cstdint>

// ------------------------------------------------------------------
// Problem constants
// ------------------------------------------------------------------
constexpr int N_ROWS = 8192;
constexpr int DIM    = 1024;
constexpr float SQRT_INV_TEMP = 2.23606797749978969f;   // sqrt(1/0.2)

constexpr int TM = 128;               // CTA tile rows
constexpr int TN = 128;               // CTA tile cols
constexpr int TK = 64;                // bf16 K elems per stage (128 B rows)
constexpr int STAGES  = 3;
constexpr int THREADS = 256;          // 8 warps, 2 (M) x 4 (N)
constexpr int NKC = DIM / TK;         // 16 K chunks

constexpr int A_BYTES   = TM * TK * 2;            // 16 KB
constexpr int B_BYTES   = TN * TK * 2;            // 16 KB
constexpr int STG_BYTES = A_BYTES + B_BYTES;      // 32 KB
constexpr int SMEM_BYTES = STAGES * STG_BYTES;    // 96 KB

constexpr int NTILE = N_ROWS / TM;                // 64
constexpr int NTRI  = NTILE * (NTILE + 1) / 2;    // 2080 upper-tri tiles
constexpr int NSLOT = NTILE;                      // 64 scratch slots per row
// Per row r in row-tile tr: dir-1 (tiles (tr,tn), tn>=tr) writes slots tn>=tr;
// dir-2 (tiles (tm,tr), tm<tr) writes slots tm<tr. Union = all 64 slots,
// each exactly once -> no zero-fill needed.

// ------------------------------------------------------------------
// Device scratch (static globals: allocation-free)
// ------------------------------------------------------------------
__device__ __nv_bfloat16 g_x[(size_t)N_ROWS * DIM];   // normalized * sqrt(5)
__device__ float g_ps[NSLOT * N_ROWS];                // partial sum exp(sim)
__device__ float g_pa[NSLOT * N_ROWS];                // partial sum lbl*sim
__device__ float g_pb[NSLOT * N_ROWS];                // partial sum lbl
__device__ float g_rowloss[N_ROWS];

// ------------------------------------------------------------------
// PTX helpers
// ------------------------------------------------------------------
__device__ __forceinline__ uint32_t smem_u32(const void* p) {
    uint32_t a;
    asm("{ .reg .u64 t; cvta.to.shared.u64 t, %1; cvt.u32.u64 %0, t; }" : "=r"(a) : "l"(p));
    return a;
}

__device__ __forceinline__ void cp_async16(uint32_t dst, const void* src) {
    asm volatile("{ .reg .u64 g; cvta.to.global.u64 g, %1; "
                 "cp.async.cg.shared.global [%0], [g], 16; }"
                 :: "r"(dst), "l"(src) : "memory");
}
#define CP_COMMIT() asm volatile("cp.async.commit_group;" ::: "memory")
#define CP_WAIT(N)  asm volatile("cp.async.wait_group %0;" :: "n"(N) : "memory")

#define LDSM_X4(R0, R1, R2, R3, ADDR) \
    asm volatile("ldmatrix.sync.aligned.m8n8.x4.shared.b16 {%0,%1,%2,%3}, [%4];" \
                 : "=r"(R0), "=r"(R1), "=r"(R2), "=r"(R3) : "r"(ADDR))

__device__ __forceinline__ void mma_bf16(float* d, const uint32_t* a, const uint32_t* b) {
    asm volatile(
        "mma.sync.aligned.m16n8k16.row.col.f32.bf16.bf16.f32 "
        "{%0,%1,%2,%3}, {%4,%5,%6,%7}, {%8,%9}, {%0,%1,%2,%3};"
        : "+f"(d[0]), "+f"(d[1]), "+f"(d[2]), "+f"(d[3])
        : "r"(a[0]), "r"(a[1]), "r"(a[2]), "r"(a[3]), "r"(b[0]), "r"(b[1]));
}

// ------------------------------------------------------------------
// Kernel 1: row-normalize, fold sqrt(1/T), cast to bf16
// ------------------------------------------------------------------
__global__ __launch_bounds__(256) void coref_norm_kernel(const float* __restrict__ e) {
    const int row = blockIdx.x, t = threadIdx.x;
    const float* r = e + (size_t)row * DIM;
    float x0 = r[t], x1 = r[t + 256], x2 = r[t + 512], x3 = r[t + 768];
    float ss = x0 * x0 + x1 * x1 + x2 * x2 + x3 * x3;
    #pragma unroll
    for (int o = 16; o > 0; o >>= 1) ss += __shfl_xor_sync(0xffffffffu, ss, o);
    __shared__ float ws[8];
    if ((t & 31) == 0) ws[t >> 5] = ss;
    __syncthreads();
    float tot = ws[0] + ws[1] + ws[2] + ws[3] + ws[4] + ws[5] + ws[6] + ws[7];
    float scale = SQRT_INV_TEMP / fmaxf(sqrtf(tot), 1e-8f);
    __nv_bfloat16* op = g_x + (size_t)row * DIM;
    op[t]       = __float2bfloat16(x0 * scale);
    op[t + 256] = __float2bfloat16(x1 * scale);
    op[t + 512] = __float2bfloat16(x2 * scale);
    op[t + 768] = __float2bfloat16(x3 * scale);
}

// ------------------------------------------------------------------
// Kernel 2: fused upper-triangular tile GEMM (mma.sync bf16)
//           + two-direction softmax/label epilogue (sim is symmetric)
// ------------------------------------------------------------------
__device__ __forceinline__ void load_stage(uint32_t sbuf, int row_a, int row_b,
                                           int kc, int tid) {
    const __nv_bfloat16* gA = g_x + (size_t)row_a * DIM + kc * TK;
    #pragma unroll
    for (int i = 0; i < 4; ++i) {                 // A: 128 rows x 8 chunks (16B)
        int id = tid + (i << 8);
        int r = id >> 3, c = id & 7;
        uint32_t sw = (uint32_t)(r * 128) + (uint32_t)((c ^ (r & 7)) << 4);
        cp_async16(sbuf + sw, gA + (size_t)r * DIM + c * 8);
    }
    const __nv_bfloat16* gB = g_x + (size_t)row_b * DIM + kc * TK;
    uint32_t bb = sbuf + A_BYTES;
    #pragma unroll
    for (int i = 0; i < 4; ++i) {                 // B: 128 rows x 8 chunks
        int id = tid + (i << 8);
        int r = id >> 3, c = id & 7;
        uint32_t sw = (uint32_t)(r * 128) + (uint32_t)((c ^ (r & 7)) << 4);
        cp_async16(bb + sw, gB + (size_t)r * DIM + c * 8);
    }
}

__global__ __launch_bounds__(THREADS, 2)
void coref_main_kernel(const float* __restrict__ labels) {
    extern __shared__ char smem_raw[];
    const uint32_t sb = smem_u32(smem_raw);

    const int tid  = threadIdx.x;
    const int lane = tid & 31;
    const int warp = tid >> 5;
    const int warp_m = warp & 1;        // 0..1 -> 64-row half
    const int warp_n = warp >> 1;       // 0..3 -> 32-col stripe

    // Decode blockIdx.x -> upper-triangular (tm, tn), tm <= tn
    int brem = blockIdx.x, tm = 0;
    while (brem >= NTILE - tm) { brem -= NTILE - tm; ++tm; }
    const int tn = tm + brem;
    const int row0 = tm * TM;
    const int col0 = tn * TN;
    const bool offdiag = (tm != tn);

    // Prologue: prefetch stages 0,1
    load_stage(sb,              row0, col0, 0, tid); CP_COMMIT();
    load_stage(sb + STG_BYTES,  row0, col0, 1, tid); CP_COMMIT();

    float acc[4][4][4];                          // [mi][ni][frag]
    #pragma unroll
    for (int mi = 0; mi < 4; ++mi)
        #pragma unroll
        for (int ni = 0; ni < 4; ++ni)
            #pragma unroll
            for (int j = 0; j < 4; ++j) acc[mi][ni][j] = 0.f;

    // ldmatrix lane addressing
    const int a_row_in = (lane & 7) + ((lane >> 3) & 1) * 8;
    const int a_hi     = lane >> 4;
    const int b_row_in = (lane & 7) + (lane >> 4) * 8;
    const int b_hi     = (lane >> 3) & 1;

    int a_rowbyte[4], a_rx[4];
    #pragma unroll
    for (int mi = 0; mi < 4; ++mi) {
        int r = warp_m * 64 + mi * 16 + a_row_in;
        a_rowbyte[mi] = r * 128;
        a_rx[mi] = r & 7;
    }
    int b_rowbyte[2], b_rx[2];
    #pragma unroll
    for (int g = 0; g < 2; ++g) {
        int r = warp_n * 32 + g * 16 + b_row_in;
        b_rowbyte[g] = r * 128;
        b_rx[g] = r & 7;
    }

    for (int kc = 0; kc < NKC; ++kc) {
        if (kc == NKC - 1) { CP_WAIT(0); } else { CP_WAIT(1); }
        __syncthreads();

        if (kc + 2 < NKC) {
            load_stage(sb + ((kc + 2) % STAGES) * STG_BYTES, row0, col0, kc + 2, tid);
            CP_COMMIT();
        }

        const uint32_t sA = sb + (kc % STAGES) * STG_BYTES;
        const uint32_t sB = sA + A_BYTES;

        #pragma unroll
        for (int kk = 0; kk < 4; ++kk) {
            const int kk2 = kk * 2;
            uint32_t Af[4][4], Bf[4][2];
            #pragma unroll
            for (int mi = 0; mi < 4; ++mi) {
                uint32_t addr = sA + a_rowbyte[mi]
                              + (uint32_t)(((kk2 + a_hi) ^ a_rx[mi]) << 4);
                LDSM_X4(Af[mi][0], Af[mi][1], Af[mi][2], Af[mi][3], addr);
            }
            #pragma unroll
            for (int g = 0; g < 2; ++g) {
                uint32_t q0, q1, q2, q3;
                uint32_t addr = sB + b_rowbyte[g]
                              + (uint32_t)(((kk2 + b_hi) ^ b_rx[g]) << 4);
                LDSM_X4(q0, q1, q2, q3, addr);
                Bf[g * 2 + 0][0] = q0; Bf[g * 2 + 0][1] = q1;
                Bf[g * 2 + 1][0] = q2; Bf[g * 2 + 1][1] = q3;
            }
            #pragma unroll
            for (int mi = 0; mi < 4; ++mi)
                #pragma unroll
                for (int ni = 0; ni < 4; ++ni)
                    mma_bf16(acc[mi][ni], Af[mi], Bf[ni]);
        }
    }

    // ---------------- epilogue ----------------
    // Fragment: rows qrow, qrow+8; cols 2*(lane%4), +1
    const int qrow = lane >> 2;        // 0..7
    const int qcol = (lane & 3) * 2;   // 0,2,4,6

    // smem reduction buffers overlay the (now idle) pipeline stages.
    // Layout: red[0..511] = s[warp_sub][128], red[512..1023] = a, red[1024..1535] = b
    float* red = (float*)smem_raw;
    __syncthreads();   // GEMM smem reads (stage 0 live at kc=15) must drain first

    // ---- pass 1: row partials for m-block rows (dir-1), CTA-reduced -> slot tn ----
    #pragma unroll
    for (int mi = 0; mi < 4; ++mi) {
        #pragma unroll
        for (int h = 0; h < 2; ++h) {
            const int rloc = warp_m * 64 + mi * 16 + qrow + h * 8;
            const int grow = row0 + rloc;
            const float* lrow = labels + (size_t)grow * N_ROWS + col0 + warp_n * 32;
            float s = 0.f, a = 0.f, b = 0.f;
            #pragma unroll
            for (int ni = 0; ni < 4; ++ni) {
                const int gcol = col0 + warp_n * 32 + ni * 8 + qcol;
                float2 lv = __ldcs((const float2*)(lrow + ni * 8 + qcol));
                float s0 = acc[mi][ni][h * 2 + 0];
                float s1 = acc[mi][ni][h * 2 + 1];
                if (gcol != grow) {                  // only binds on diag tiles
                    s += __expf(s0);
                    a = fmaf(lv.x, s0, a);
                    b += lv.x;
                }
                if (gcol + 1 != grow) {
                    s += __expf(s1);
                    a = fmaf(lv.y, s1, a);
                    b += lv.y;
                }
            }
            s += __shfl_xor_sync(0xffffffffu, s, 1);
            s += __shfl_xor_sync(0xffffffffu, s, 2);
            a += __shfl_xor_sync(0xffffffffu, a, 1);
            a += __shfl_xor_sync(0xffffffffu, a, 2);
            b += __shfl_xor_sync(0xffffffffu, b, 1);
            b += __shfl_xor_sync(0xffffffffu, b, 2);
            if ((lane & 3) == 0) {
                red[       warp_n * 128 + rloc] = s;
                red[512  + warp_n * 128 + rloc] = a;
                red[1024 + warp_n * 128 + rloc] = b;
            }
        }
    }
    __syncthreads();
    if (tid < 128) {
        float S = red[tid]       + red[128 + tid]        + red[256 + tid]        + red[384 + tid];
        float A = red[512 + tid] + red[512 + 128 + tid]  + red[512 + 256 + tid]  + red[512 + 384 + tid];
        float B = red[1024 + tid]+ red[1024 + 128 + tid] + red[1024 + 256 + tid] + red[1024 + 384 + tid];
        g_ps[tn * N_ROWS + row0 + tid] = S;
        g_pa[tn * N_ROWS + row0 + tid] = A;
        g_pb[tn * N_ROWS + row0 + tid] = B;
    }

    // ---- pass 2 (off-diag only): column partials (dir-2), CTA-reduced -> slot tm ----
    if (offdiag) {
        float vs[4][2], va[4][2], vb[4][2];   // per-ni results at lanes 0..3
        #pragma unroll
        for (int ni = 0; ni < 4; ++ni) {
            const int gc0 = col0 + warp_n * 32 + ni * 8 + qcol;   // output rows gc0, gc0+1
            const float* lc0 = labels + (size_t)gc0 * N_ROWS;
            const float* lc1 = lc0 + N_ROWS;
            float s0 = 0.f, s1 = 0.f, a0 = 0.f, a1 = 0.f, b0 = 0.f, b1 = 0.f;
            #pragma unroll
            for (int mi = 0; mi < 4; ++mi) {
                #pragma unroll
                for (int h = 0; h < 2; ++h) {
                    const int grow = row0 + warp_m * 64 + mi * 16 + h * 8 + qrow;
                    float v0 = acc[mi][ni][h * 2 + 0];
                    float v1 = acc[mi][ni][h * 2 + 1];
                    float l0 = __ldcs(lc0 + grow);     // lbl[gc0][grow]
                    float l1 = __ldcs(lc1 + grow);     // lbl[gc0+1][grow]
                    s0 += __expf(v0);
                    s1 += __expf(v1);
                    a0 = fmaf(l0, v0, a0);
                    a1 = fmaf(l1, v1, a1);
                    b0 += l0;
                    b1 += l1;
                }
            }
            #pragma unroll
            for (int o = 4; o <= 16; o <<= 1) {
                s0 += __shfl_xor_sync(0xffffffffu, s0, o);
                s1 += __shfl_xor_sync(0xffffffffu, s1, o);
                a0 += __shfl_xor_sync(0xffffffffu, a0, o);
                a1 += __shfl_xor_sync(0xffffffffu, a1, o);
                b0 += __shfl_xor_sync(0xffffffffu, b0, o);
                b1 += __shfl_xor_sync(0xffffffffu, b1, o);
            }
            vs[ni][0] = s0; vs[ni][1] = s1;
            va[ni][0] = a0; va[ni][1] = a1;
            vb[ni][0] = b0; vb[ni][1] = b1;
        }
        __syncthreads();   // pass-1 smem reads done before overwrite
        if (qrow == 0) {   // lanes 0..3 hold the reduced values
            #pragma unroll
            for (int ni = 0; ni < 4; ++ni) {
                const int cloc = warp_n * 32 + ni * 8 + qcol;   // 0..127
                red[       warp_m * 128 + cloc]     = vs[ni][0];
                red[       warp_m * 128 + cloc + 1] = vs[ni][1];
                red[512  + warp_m * 128 + cloc]     = va[ni][0];
                red[512  + warp_m * 128 + cloc + 1] = va[ni][1];
                red[1024 + warp_m * 128 + cloc]     = vb[ni][0];
                red[1024 + warp_m * 128 + cloc + 1] = vb[ni][1];
            }
        }
        __syncthreads();
        if (tid < 128) {
            float S = red[tid]        + red[128 + tid];
            float A = red[512 + tid]  + red[512 + 128 + tid];
            float B = red[1024 + tid] + red[1024 + 128 + tid];
            g_ps[tm * N_ROWS + col0 + tid] = S;
            g_pa[tm * N_ROWS + col0 + tid] = A;
            g_pb[tm * N_ROWS + col0 + tid] = B;
        }
    }
}

// ------------------------------------------------------------------
// Kernel 3: per-row reduction of the 64 slot partials (coalesced, high-MLP)
// CTA = 256 threads: tid%32 -> row within 32-row group, tid/32 -> slot group of 8
// ------------------------------------------------------------------
__global__ __launch_bounds__(256) void coref_rowloss_kernel() {
    const int rlane = threadIdx.x & 31;
    const int grp   = threadIdx.x >> 5;            // 0..7
    const int row   = blockIdx.x * 32 + rlane;
    float S = 0.f, A = 0.f, B = 0.f;
    #pragma unroll
    for (int k = 0; k < 8; ++k) {
        const int t = grp * 8 + k;
        S += g_ps[t * N_ROWS + row];
        A += g_pa[t * N_ROWS + row];
        B += g_pb[t * N_ROWS + row];
    }
    __shared__ float ss[8][32], sa[8][32], sb2[8][32];
    ss[grp][rlane] = S; sa[grp][rlane] = A; sb2[grp][rlane] = B;
    __syncthreads();
    if (grp == 0) {
        float St = 0.f, At = 0.f, Bt = 0.f;
        #pragma unroll
        for (int g = 0; g < 8; ++g) {
            St += ss[g][rlane]; At += sa[g][rlane]; Bt += sb2[g][rlane];
        }
        // loss_i = lse_i * B_i - A_i   (no max shift: |sim| <= 5)
        g_rowloss[row] = logf(St) * Bt - At;
    }
}

// ------------------------------------------------------------------
// Kernel 4: deterministic fixed-tree scalar reduce (mean over rows)
// ------------------------------------------------------------------
__global__ __launch_bounds__(256) void coref_final_kernel(float* __restrict__ out) {
    __shared__ float sm[256];
    const int t = threadIdx.x;
    float v = 0.f;
    for (int i = t; i < N_ROWS; i += 256) v += g_rowloss[i];
    sm[t] = v;
    __syncthreads();
    #pragma unroll
    for (int s = 128; s > 0; s >>= 1) {
        if (t < s) sm[t] += sm[t + s];
        __syncthreads();
    }
    if (t == 0) out[0] = sm[0] * (1.0f / (float)N_ROWS);
}

// ------------------------------------------------------------------
// Launcher (graph-capturable)
// ------------------------------------------------------------------
extern "C" void kernel_launch(void* const* d_in, const int* in_sizes, int n_in,
                              void* d_out, int out_size) {
    const float* embs   = (const float*)d_in[0];
    const float* labels = (const float*)d_in[1];
    if (n_in >= 2 && in_sizes[0] == N_ROWS * N_ROWS) {  // defensive input-order check
        const float* tmp = embs; embs = labels; labels = tmp;
    }
    float* out = (float*)d_out;

    cudaFuncSetAttribute(coref_main_kernel,
                         cudaFuncAttributeMaxDynamicSharedMemorySize, SMEM_BYTES);

    coref_norm_kernel<<<N_ROWS, 256>>>(embs);
    coref_main_kernel<<<NTRI, THREADS, SMEM_BYTES>>>(labels);
    coref_rowloss_kernel<<<N_ROWS / 32, 256>>>();
    coref_final_kernel<<<1, 256>>>(out);
}

// round 8
// speedup vs baseline: 1.4418x; 1.4418x over previous
#include <cuda_runtime.h>
#include <cuda_bf16.h>
#include <cstdint>

// ------------------------------------------------------------------
// Problem constants
// ------------------------------------------------------------------
constexpr int N_ROWS = 8192;
constexpr int DIM    = 1024;
constexpr float SQRT_INV_TEMP = 2.23606797749978969f;   // sqrt(1/0.2)

constexpr int TM = 128;               // CTA tile rows
constexpr int TN = 128;               // CTA tile cols
constexpr int TK = 64;                // bf16 K elems per stage (128 B rows)
constexpr int STAGES  = 3;
constexpr int THREADS = 256;          // 8 warps, 2 (M) x 4 (N)
constexpr int NKC = DIM / TK;         // 16 K chunks

constexpr int A_BYTES   = TM * TK * 2;            // 16 KB
constexpr int B_BYTES   = TN * TK * 2;            // 16 KB
constexpr int STG_BYTES = A_BYTES + B_BYTES;      // 32 KB
constexpr int SMEM_BYTES = STAGES * STG_BYTES;    // 96 KB

constexpr int NTILE   = N_ROWS / TM;              // 64
constexpr int NTRI    = NTILE * (NTILE + 1) / 2;  // 2080 upper-tri tiles
constexpr int NSTRIPE = N_ROWS / 32;              // 256 scratch slots per row

// ------------------------------------------------------------------
// Device scratch (static globals: allocation-free)
// ------------------------------------------------------------------
__device__ __nv_bfloat16 g_x[(size_t)N_ROWS * DIM];   // normalized * sqrt(5)
__device__ float g_ps[NSTRIPE * N_ROWS];              // partial sum exp(sim)
__device__ float g_pa[NSTRIPE * N_ROWS];              // partial sum lbl*sim
__device__ float g_pb[NSTRIPE * N_ROWS];              // partial sum lbl
__device__ float g_rowloss[N_ROWS];

// ------------------------------------------------------------------
// PTX helpers
// ------------------------------------------------------------------
__device__ __forceinline__ uint32_t smem_u32(const void* p) {
    uint32_t a;
    asm("{ .reg .u64 t; cvta.to.shared.u64 t, %1; cvt.u32.u64 %0, t; }" : "=r"(a) : "l"(p));
    return a;
}

__device__ __forceinline__ void cp_async16(uint32_t dst, const void* src) {
    asm volatile("{ .reg .u64 g; cvta.to.global.u64 g, %1; "
                 "cp.async.cg.shared.global [%0], [g], 16; }"
                 :: "r"(dst), "l"(src) : "memory");
}
#define CP_COMMIT() asm volatile("cp.async.commit_group;" ::: "memory")
#define CP_WAIT(N)  asm volatile("cp.async.wait_group %0;" :: "n"(N) : "memory")

#define LDSM_X4(R0, R1, R2, R3, ADDR) \
    asm volatile("ldmatrix.sync.aligned.m8n8.x4.shared.b16 {%0,%1,%2,%3}, [%4];" \
                 : "=r"(R0), "=r"(R1), "=r"(R2), "=r"(R3) : "r"(ADDR))

__device__ __forceinline__ void mma_bf16(float* d, const uint32_t* a, const uint32_t* b) {
    asm volatile(
        "mma.sync.aligned.m16n8k16.row.col.f32.bf16.bf16.f32 "
        "{%0,%1,%2,%3}, {%4,%5,%6,%7}, {%8,%9}, {%0,%1,%2,%3};"
        : "+f"(d[0]), "+f"(d[1]), "+f"(d[2]), "+f"(d[3])
        : "r"(a[0]), "r"(a[1]), "r"(a[2]), "r"(a[3]), "r"(b[0]), "r"(b[1]));
}

// ------------------------------------------------------------------
// Kernel 0: zero the scratch partial arrays (some slots never written
// under the triangular grid; kernel 3 sums all slots)
// ------------------------------------------------------------------
__global__ __launch_bounds__(256) void coref_zero_kernel() {
    const int i = blockIdx.x * 256 + threadIdx.x;   // grid covers exactly NSTRIPE*N_ROWS
    g_ps[i] = 0.f; g_pa[i] = 0.f; g_pb[i] = 0.f;
}

// ------------------------------------------------------------------
// Kernel 1: row-normalize, fold sqrt(1/T), cast to bf16
// ------------------------------------------------------------------
__global__ __launch_bounds__(256) void coref_norm_kernel(const float* __restrict__ e) {
    const int row = blockIdx.x, t = threadIdx.x;
    const float* r = e + (size_t)row * DIM;
    float x0 = r[t], x1 = r[t + 256], x2 = r[t + 512], x3 = r[t + 768];
    float ss = x0 * x0 + x1 * x1 + x2 * x2 + x3 * x3;
    #pragma unroll
    for (int o = 16; o > 0; o >>= 1) ss += __shfl_xor_sync(0xffffffffu, ss, o);
    __shared__ float ws[8];
    if ((t & 31) == 0) ws[t >> 5] = ss;
    __syncthreads();
    float tot = ws[0] + ws[1] + ws[2] + ws[3] + ws[4] + ws[5] + ws[6] + ws[7];
    float scale = SQRT_INV_TEMP / fmaxf(sqrtf(tot), 1e-8f);
    __nv_bfloat16* op = g_x + (size_t)row * DIM;
    op[t]       = __float2bfloat16(x0 * scale);
    op[t + 256] = __float2bfloat16(x1 * scale);
    op[t + 512] = __float2bfloat16(x2 * scale);
    op[t + 768] = __float2bfloat16(x3 * scale);
}

// ------------------------------------------------------------------
// Kernel 2: fused upper-triangular tile GEMM (mma.sync bf16)
//           + two-direction softmax/label epilogue (sim is symmetric)
// (identical to the 260.4us R3 version — register-critical, do not touch)
// ------------------------------------------------------------------
__device__ __forceinline__ void load_stage(uint32_t sbuf, int row_a, int row_b,
                                           int kc, int tid) {
    const __nv_bfloat16* gA = g_x + (size_t)row_a * DIM + kc * TK;
    #pragma unroll
    for (int i = 0; i < 4; ++i) {                 // A: 128 rows x 8 chunks (16B)
        int id = tid + (i << 8);
        int r = id >> 3, c = id & 7;
        uint32_t sw = (uint32_t)(r * 128) + (uint32_t)((c ^ (r & 7)) << 4);
        cp_async16(sbuf + sw, gA + (size_t)r * DIM + c * 8);
    }
    const __nv_bfloat16* gB = g_x + (size_t)row_b * DIM + kc * TK;
    uint32_t bb = sbuf + A_BYTES;
    #pragma unroll
    for (int i = 0; i < 4; ++i) {                 // B: 128 rows x 8 chunks
        int id = tid + (i << 8);
        int r = id >> 3, c = id & 7;
        uint32_t sw = (uint32_t)(r * 128) + (uint32_t)((c ^ (r & 7)) << 4);
        cp_async16(bb + sw, gB + (size_t)r * DIM + c * 8);
    }
}

__global__ __launch_bounds__(THREADS, 2)
void coref_main_kernel(const float* __restrict__ labels) {
    extern __shared__ char smem_raw[];
    const uint32_t sb = smem_u32(smem_raw);

    const int tid  = threadIdx.x;
    const int lane = tid & 31;
    const int warp = tid >> 5;
    const int warp_m = warp & 1;        // 0..1 -> 64-row half
    const int warp_n = warp >> 1;       // 0..3 -> 32-col stripe

    // Decode blockIdx.x -> upper-triangular (tm, tn), tm <= tn
    int brem = blockIdx.x, tm = 0;
    while (brem >= NTILE - tm) { brem -= NTILE - tm; ++tm; }
    const int tn = tm + brem;
    const int row0 = tm * TM;
    const int col0 = tn * TN;
    const bool offdiag = (tm != tn);

    // Prologue: prefetch stages 0,1
    load_stage(sb,              row0, col0, 0, tid); CP_COMMIT();
    load_stage(sb + STG_BYTES,  row0, col0, 1, tid); CP_COMMIT();

    float acc[4][4][4];                          // [mi][ni][frag]
    #pragma unroll
    for (int mi = 0; mi < 4; ++mi)
        #pragma unroll
        for (int ni = 0; ni < 4; ++ni)
            #pragma unroll
            for (int j = 0; j < 4; ++j) acc[mi][ni][j] = 0.f;

    // ldmatrix lane addressing
    const int a_row_in = (lane & 7) + ((lane >> 3) & 1) * 8;
    const int a_hi     = lane >> 4;
    const int b_row_in = (lane & 7) + (lane >> 4) * 8;
    const int b_hi     = (lane >> 3) & 1;

    int a_rowbyte[4], a_rx[4];
    #pragma unroll
    for (int mi = 0; mi < 4; ++mi) {
        int r = warp_m * 64 + mi * 16 + a_row_in;
        a_rowbyte[mi] = r * 128;
        a_rx[mi] = r & 7;
    }
    int b_rowbyte[2], b_rx[2];
    #pragma unroll
    for (int g = 0; g < 2; ++g) {
        int r = warp_n * 32 + g * 16 + b_row_in;
        b_rowbyte[g] = r * 128;
        b_rx[g] = r & 7;
    }

    for (int kc = 0; kc < NKC; ++kc) {
        if (kc == NKC - 1) { CP_WAIT(0); } else { CP_WAIT(1); }
        __syncthreads();

        if (kc + 2 < NKC) {
            load_stage(sb + ((kc + 2) % STAGES) * STG_BYTES, row0, col0, kc + 2, tid);
            CP_COMMIT();
        }

        const uint32_t sA = sb + (kc % STAGES) * STG_BYTES;
        const uint32_t sB = sA + A_BYTES;

        #pragma unroll
        for (int kk = 0; kk < 4; ++kk) {
            const int kk2 = kk * 2;
            uint32_t Af[4][4], Bf[4][2];
            #pragma unroll
            for (int mi = 0; mi < 4; ++mi) {
                uint32_t addr = sA + a_rowbyte[mi]
                              + (uint32_t)(((kk2 + a_hi) ^ a_rx[mi]) << 4);
                LDSM_X4(Af[mi][0], Af[mi][1], Af[mi][2], Af[mi][3], addr);
            }
            #pragma unroll
            for (int g = 0; g < 2; ++g) {
                uint32_t q0, q1, q2, q3;
                uint32_t addr = sB + b_rowbyte[g]
                              + (uint32_t)(((kk2 + b_hi) ^ b_rx[g]) << 4);
                LDSM_X4(q0, q1, q2, q3, addr);
                Bf[g * 2 + 0][0] = q0; Bf[g * 2 + 0][1] = q1;
                Bf[g * 2 + 1][0] = q2; Bf[g * 2 + 1][1] = q3;
            }
            #pragma unroll
            for (int mi = 0; mi < 4; ++mi)
                #pragma unroll
                for (int ni = 0; ni < 4; ++ni)
                    mma_bf16(acc[mi][ni], Af[mi], Bf[ni]);
        }
    }

    // ---------------- epilogue ----------------
    // Fragment: rows qrow, qrow+8; cols 2*(lane%4), +1
    const int qrow = lane >> 2;        // 0..7
    const int qcol = (lane & 3) * 2;   // 0,2,4,6

    // ---- pass 1: row partials for m-block rows (dir-1) ----
    {
        const int stripe = tn * 4 + warp_n;
        #pragma unroll
        for (int mi = 0; mi < 4; ++mi) {
            #pragma unroll
            for (int h = 0; h < 2; ++h) {
                const int grow = row0 + warp_m * 64 + mi * 16 + qrow + h * 8;
                const float* lrow = labels + (size_t)grow * N_ROWS + col0 + warp_n * 32;
                float s = 0.f, a = 0.f, b = 0.f;
                #pragma unroll
                for (int ni = 0; ni < 4; ++ni) {
                    const int gcol = col0 + warp_n * 32 + ni * 8 + qcol;
                    float2 lv = __ldcs((const float2*)(lrow + ni * 8 + qcol));
                    float s0 = acc[mi][ni][h * 2 + 0];
                    float s1 = acc[mi][ni][h * 2 + 1];
                    if (gcol != grow) {                  // only binds on diag tiles
                        s += __expf(s0);
                        a = fmaf(lv.x, s0, a);
                        b += lv.x;
                    }
                    if (gcol + 1 != grow) {
                        s += __expf(s1);
                        a = fmaf(lv.y, s1, a);
                        b += lv.y;
                    }
                }
                s += __shfl_xor_sync(0xffffffffu, s, 1);
                s += __shfl_xor_sync(0xffffffffu, s, 2);
                a += __shfl_xor_sync(0xffffffffu, a, 1);
                a += __shfl_xor_sync(0xffffffffu, a, 2);
                b += __shfl_xor_sync(0xffffffffu, b, 1);
                b += __shfl_xor_sync(0xffffffffu, b, 2);
                if ((lane & 3) == 0) {
                    g_ps[stripe * N_ROWS + grow] = s;
                    g_pa[stripe * N_ROWS + grow] = a;
                    g_pb[stripe * N_ROWS + grow] = b;
                }
            }
        }
    }

    // ---- pass 2 (off-diag only): column partials for n-block rows (dir-2) ----
    if (offdiag) {
        const int slot = tm * 4 + warp_m * 2;
        #pragma unroll
        for (int ni = 0; ni < 4; ++ni) {
            const int gc0 = col0 + warp_n * 32 + ni * 8 + qcol;   // output rows gc0, gc0+1
            const float* lc0 = labels + (size_t)gc0 * N_ROWS;
            const float* lc1 = lc0 + N_ROWS;
            float s0 = 0.f, s1 = 0.f, a0 = 0.f, a1 = 0.f, b0 = 0.f, b1 = 0.f;
            #pragma unroll
            for (int mi = 0; mi < 4; ++mi) {
                #pragma unroll
                for (int h = 0; h < 2; ++h) {
                    const int grow = row0 + warp_m * 64 + mi * 16 + h * 8 + qrow;
                    float v0 = acc[mi][ni][h * 2 + 0];
                    float v1 = acc[mi][ni][h * 2 + 1];
                    float l0 = __ldcs(lc0 + grow);     // lbl[gc0][grow]
                    float l1 = __ldcs(lc1 + grow);     // lbl[gc0+1][grow]
                    s0 += __expf(v0);
                    s1 += __expf(v1);
                    a0 = fmaf(l0, v0, a0);
                    a1 = fmaf(l1, v1, a1);
                    b0 += l0;
                    b1 += l1;
                }
            }
            #pragma unroll
            for (int o = 4; o <= 16; o <<= 1) {
                s0 += __shfl_xor_sync(0xffffffffu, s0, o);
                s1 += __shfl_xor_sync(0xffffffffu, s1, o);
                a0 += __shfl_xor_sync(0xffffffffu, a0, o);
                a1 += __shfl_xor_sync(0xffffffffu, a1, o);
                b0 += __shfl_xor_sync(0xffffffffu, b0, o);
                b1 += __shfl_xor_sync(0xffffffffu, b1, o);
            }
            if (qrow == 0) {
                g_ps[slot * N_ROWS + gc0]     = s0;
                g_ps[slot * N_ROWS + gc0 + 1] = s1;
                g_pa[slot * N_ROWS + gc0]     = a0;
                g_pa[slot * N_ROWS + gc0 + 1] = a1;
                g_pb[slot * N_ROWS + gc0]     = b0;
                g_pb[slot * N_ROWS + gc0 + 1] = b1;
            }
        }
    }
}

// ------------------------------------------------------------------
// Kernel 3: per-row reduction of the 256 stripe partials.
// Restructured (R3 ncu: 43us, 64 CTAs, occ 6%, 0.59 TB/s): now 256 CTAs x 256
// threads; tid%32 -> row (coalesced 128B lines), tid/32 -> group of 32 slots,
// unrolled for MLP; smem tree across the 8 groups.
// ------------------------------------------------------------------
__global__ __launch_bounds__(256) void coref_rowloss_kernel() {
    const int rlane = threadIdx.x & 31;
    const int grp   = threadIdx.x >> 5;            // 0..7
    const int row   = blockIdx.x * 32 + rlane;
    float S = 0.f, A = 0.f, B = 0.f;
    #pragma unroll 8
    for (int k = 0; k < 32; ++k) {
        const int t = grp * 32 + k;
        S += g_ps[t * N_ROWS + row];
        A += g_pa[t * N_ROWS + row];
        B += g_pb[t * N_ROWS + row];
    }
    __shared__ float ss[8][32], sa[8][32], sb2[8][32];
    ss[grp][rlane] = S; sa[grp][rlane] = A; sb2[grp][rlane] = B;
    __syncthreads();
    if (grp == 0) {
        float St = 0.f, At = 0.f, Bt = 0.f;
        #pragma unroll
        for (int g = 0; g < 8; ++g) {
            St += ss[g][rlane]; At += sa[g][rlane]; Bt += sb2[g][rlane];
        }
        // loss_i = lse_i * B_i - A_i   (no max shift: |sim| <= 5)
        g_rowloss[row] = logf(St) * Bt - At;
    }
}

// ------------------------------------------------------------------
// Kernel 4: deterministic fixed-tree scalar reduce (mean over rows)
// ------------------------------------------------------------------
__global__ __launch_bounds__(256) void coref_final_kernel(float* __restrict__ out) {
    __shared__ float sm[256];
    const int t = threadIdx.x;
    float v = 0.f;
    for (int i = t; i < N_ROWS; i += 256) v += g_rowloss[i];
    sm[t] = v;
    __syncthreads();
    #pragma unroll
    for (int s = 128; s > 0; s >>= 1) {
        if (t < s) sm[t] += sm[t + s];
        __syncthreads();
    }
    if (t == 0) out[0] = sm[0] * (1.0f / (float)N_ROWS);
}

// ------------------------------------------------------------------
// Launcher (graph-capturable)
// ------------------------------------------------------------------
extern "C" void kernel_launch(void* const* d_in, const int* in_sizes, int n_in,
                              void* d_out, int out_size) {
    const float* embs   = (const float*)d_in[0];
    const float* labels = (const float*)d_in[1];
    if (n_in >= 2 && in_sizes[0] == N_ROWS * N_ROWS) {  // defensive input-order check
        const float* tmp = embs; embs = labels; labels = tmp;
    }
    float* out = (float*)d_out;

    cudaFuncSetAttribute(coref_main_kernel,
                         cudaFuncAttributeMaxDynamicSharedMemorySize, SMEM_BYTES);

    coref_zero_kernel<<<(NSTRIPE * N_ROWS) / 256, 256>>>();
    coref_norm_kernel<<<N_ROWS, 256>>>(embs);
    coref_main_kernel<<<NTRI, THREADS, SMEM_BYTES>>>(labels);
    coref_rowloss_kernel<<<N_ROWS / 32, 256>>>();
    coref_final_kernel<<<1, 256>>>(out);
}

// round 9
// speedup vs baseline: 1.4742x; 1.0225x over previous
#include <cuda_runtime.h>
#include <cuda_bf16.h>
#include <cstdint>

// ------------------------------------------------------------------
// Problem constants
// ------------------------------------------------------------------
constexpr int N_ROWS = 8192;
constexpr int DIM    = 1024;
constexpr float SQRT_INV_TEMP = 2.23606797749978969f;   // sqrt(1/0.2)

constexpr int TM = 128;               // CTA tile rows
constexpr int TN = 128;               // CTA tile cols
constexpr int TK = 64;                // bf16 K elems per stage (128 B rows)
constexpr int STAGES  = 3;
constexpr int THREADS = 256;          // 8 warps, 2 (M) x 4 (N)
constexpr int NKC = DIM / TK;         // 16 K chunks

constexpr int A_BYTES   = TM * TK * 2;            // 16 KB
constexpr int B_BYTES   = TN * TK * 2;            // 16 KB
constexpr int STG_BYTES = A_BYTES + B_BYTES;      // 32 KB
constexpr int SMEM_BYTES = STAGES * STG_BYTES;    // 96 KB

constexpr int NTILE   = N_ROWS / TM;              // 64
constexpr int NTRI    = NTILE * (NTILE + 1) / 2;  // 2080 upper-tri tiles
constexpr int NSTRIPE = N_ROWS / 32;              // 256 scratch slots per row
constexpr int NRL_CTAS = N_ROWS / 32;             // 256 rowloss CTAs

// ------------------------------------------------------------------
// Device scratch (static globals: allocation-free)
// Slot coverage for row r in row-tile tr:
//   dir-1 (tiles (tr,tn), tn>=tr): slots tn*4+{0..3}
//   dir-2 (tiles (tm,tr), tm<tr):  slots tm*4+{0,2} (values), tm*4+{1,3} (zeros)
// -> every slot written exactly once; no zero-fill kernel needed.
// ------------------------------------------------------------------
__device__ __nv_bfloat16 g_x[(size_t)N_ROWS * DIM];   // normalized * sqrt(5)
__device__ float g_ps[NSTRIPE * N_ROWS];              // partial sum exp(sim)
__device__ float g_pa[NSTRIPE * N_ROWS];              // partial sum lbl*sim
__device__ float g_pb[NSTRIPE * N_ROWS];              // partial sum lbl
__device__ float g_blocksum[NRL_CTAS];                // per-rowloss-CTA loss partials

// ------------------------------------------------------------------
// PTX helpers
// ------------------------------------------------------------------
__device__ __forceinline__ uint32_t smem_u32(const void* p) {
    uint32_t a;
    asm("{ .reg .u64 t; cvta.to.shared.u64 t, %1; cvt.u32.u64 %0, t; }" : "=r"(a) : "l"(p));
    return a;
}

__device__ __forceinline__ void cp_async16(uint32_t dst, const void* src) {
    asm volatile("{ .reg .u64 g; cvta.to.global.u64 g, %1; "
                 "cp.async.cg.shared.global [%0], [g], 16; }"
                 :: "r"(dst), "l"(src) : "memory");
}
#define CP_COMMIT() asm volatile("cp.async.commit_group;" ::: "memory")
#define CP_WAIT(N)  asm volatile("cp.async.wait_group %0;" :: "n"(N) : "memory")

#define LDSM_X4(R0, R1, R2, R3, ADDR) \
    asm volatile("ldmatrix.sync.aligned.m8n8.x4.shared.b16 {%0,%1,%2,%3}, [%4];" \
                 : "=r"(R0), "=r"(R1), "=r"(R2), "=r"(R3) : "r"(ADDR))

__device__ __forceinline__ void mma_bf16(float* d, const uint32_t* a, const uint32_t* b) {
    asm volatile(
        "mma.sync.aligned.m16n8k16.row.col.f32.bf16.bf16.f32 "
        "{%0,%1,%2,%3}, {%4,%5,%6,%7}, {%8,%9}, {%0,%1,%2,%3};"
        : "+f"(d[0]), "+f"(d[1]), "+f"(d[2]), "+f"(d[3])
        : "r"(a[0]), "r"(a[1]), "r"(a[2]), "r"(a[3]), "r"(b[0]), "r"(b[1]));
}

// ------------------------------------------------------------------
// Kernel 1: row-normalize, fold sqrt(1/T), cast to bf16
// ------------------------------------------------------------------
__global__ __launch_bounds__(256) void coref_norm_kernel(const float* __restrict__ e) {
    const int row = blockIdx.x, t = threadIdx.x;
    const float* r = e + (size_t)row * DIM;
    float x0 = r[t], x1 = r[t + 256], x2 = r[t + 512], x3 = r[t + 768];
    float ss = x0 * x0 + x1 * x1 + x2 * x2 + x3 * x3;
    #pragma unroll
    for (int o = 16; o > 0; o >>= 1) ss += __shfl_xor_sync(0xffffffffu, ss, o);
    __shared__ float ws[8];
    if ((t & 31) == 0) ws[t >> 5] = ss;
    __syncthreads();
    float tot = ws[0] + ws[1] + ws[2] + ws[3] + ws[4] + ws[5] + ws[6] + ws[7];
    float scale = SQRT_INV_TEMP / fmaxf(sqrtf(tot), 1e-8f);
    __nv_bfloat16* op = g_x + (size_t)row * DIM;
    op[t]       = __float2bfloat16(x0 * scale);
    op[t + 256] = __float2bfloat16(x1 * scale);
    op[t + 512] = __float2bfloat16(x2 * scale);
    op[t + 768] = __float2bfloat16(x3 * scale);
}

// ------------------------------------------------------------------
// Kernel 2: fused upper-triangular tile GEMM (mma.sync bf16)
//           + two-direction softmax/label epilogue (sim is symmetric)
// (GEMM body identical to the 260.4us R3 version — register-critical)
// ------------------------------------------------------------------
__device__ __forceinline__ void load_stage(uint32_t sbuf, int row_a, int row_b,
                                           int kc, int tid) {
    const __nv_bfloat16* gA = g_x + (size_t)row_a * DIM + kc * TK;
    #pragma unroll
    for (int i = 0; i < 4; ++i) {                 // A: 128 rows x 8 chunks (16B)
        int id = tid + (i << 8);
        int r = id >> 3, c = id & 7;
        uint32_t sw = (uint32_t)(r * 128) + (uint32_t)((c ^ (r & 7)) << 4);
        cp_async16(sbuf + sw, gA + (size_t)r * DIM + c * 8);
    }
    const __nv_bfloat16* gB = g_x + (size_t)row_b * DIM + kc * TK;
    uint32_t bb = sbuf + A_BYTES;
    #pragma unroll
    for (int i = 0; i < 4; ++i) {                 // B: 128 rows x 8 chunks
        int id = tid + (i << 8);
        int r = id >> 3, c = id & 7;
        uint32_t sw = (uint32_t)(r * 128) + (uint32_t)((c ^ (r & 7)) << 4);
        cp_async16(bb + sw, gB + (size_t)r * DIM + c * 8);
    }
}

__global__ __launch_bounds__(THREADS, 2)
void coref_main_kernel(const float* __restrict__ labels) {
    extern __shared__ char smem_raw[];
    const uint32_t sb = smem_u32(smem_raw);

    const int tid  = threadIdx.x;
    const int lane = tid & 31;
    const int warp = tid >> 5;
    const int warp_m = warp & 1;        // 0..1 -> 64-row half
    const int warp_n = warp >> 1;       // 0..3 -> 32-col stripe

    // Decode blockIdx.x -> upper-triangular (tm, tn), tm <= tn
    int brem = blockIdx.x, tm = 0;
    while (brem >= NTILE - tm) { brem -= NTILE - tm; ++tm; }
    const int tn = tm + brem;
    const int row0 = tm * TM;
    const int col0 = tn * TN;
    const bool offdiag = (tm != tn);

    // Prologue: prefetch stages 0,1
    load_stage(sb,              row0, col0, 0, tid); CP_COMMIT();
    load_stage(sb + STG_BYTES,  row0, col0, 1, tid); CP_COMMIT();

    float acc[4][4][4];                          // [mi][ni][frag]
    #pragma unroll
    for (int mi = 0; mi < 4; ++mi)
        #pragma unroll
        for (int ni = 0; ni < 4; ++ni)
            #pragma unroll
            for (int j = 0; j < 4; ++j) acc[mi][ni][j] = 0.f;

    // ldmatrix lane addressing
    const int a_row_in = (lane & 7) + ((lane >> 3) & 1) * 8;
    const int a_hi     = lane >> 4;
    const int b_row_in = (lane & 7) + (lane >> 4) * 8;
    const int b_hi     = (lane >> 3) & 1;

    int a_rowbyte[4], a_rx[4];
    #pragma unroll
    for (int mi = 0; mi < 4; ++mi) {
        int r = warp_m * 64 + mi * 16 + a_row_in;
        a_rowbyte[mi] = r * 128;
        a_rx[mi] = r & 7;
    }
    int b_rowbyte[2], b_rx[2];
    #pragma unroll
    for (int g = 0; g < 2; ++g) {
        int r = warp_n * 32 + g * 16 + b_row_in;
        b_rowbyte[g] = r * 128;
        b_rx[g] = r & 7;
    }

    for (int kc = 0; kc < NKC; ++kc) {
        if (kc == NKC - 1) { CP_WAIT(0); } else { CP_WAIT(1); }
        __syncthreads();

        if (kc + 2 < NKC) {
            load_stage(sb + ((kc + 2) % STAGES) * STG_BYTES, row0, col0, kc + 2, tid);
            CP_COMMIT();
        }

        const uint32_t sA = sb + (kc % STAGES) * STG_BYTES;
        const uint32_t sB = sA + A_BYTES;

        #pragma unroll
        for (int kk = 0; kk < 4; ++kk) {
            const int kk2 = kk * 2;
            uint32_t Af[4][4], Bf[4][2];
            #pragma unroll
            for (int mi = 0; mi < 4; ++mi) {
                uint32_t addr = sA + a_rowbyte[mi]
                              + (uint32_t)(((kk2 + a_hi) ^ a_rx[mi]) << 4);
                LDSM_X4(Af[mi][0], Af[mi][1], Af[mi][2], Af[mi][3], addr);
            }
            #pragma unroll
            for (int g = 0; g < 2; ++g) {
                uint32_t q0, q1, q2, q3;
                uint32_t addr = sB + b_rowbyte[g]
                              + (uint32_t)(((kk2 + b_hi) ^ b_rx[g]) << 4);
                LDSM_X4(q0, q1, q2, q3, addr);
                Bf[g * 2 + 0][0] = q0; Bf[g * 2 + 0][1] = q1;
                Bf[g * 2 + 1][0] = q2; Bf[g * 2 + 1][1] = q3;
            }
            #pragma unroll
            for (int mi = 0; mi < 4; ++mi)
                #pragma unroll
                for (int ni = 0; ni < 4; ++ni)
                    mma_bf16(acc[mi][ni], Af[mi], Bf[ni]);
        }
    }

    // ---------------- epilogue ----------------
    // Fragment: rows qrow, qrow+8; cols 2*(lane%4), +1
    const int qrow = lane >> 2;        // 0..7
    const int qcol = (lane & 3) * 2;   // 0,2,4,6

    // ---- pass 1: row partials for m-block rows (dir-1) ----
    {
        const int stripe = tn * 4 + warp_n;
        #pragma unroll
        for (int mi = 0; mi < 4; ++mi) {
            #pragma unroll
            for (int h = 0; h < 2; ++h) {
                const int grow = row0 + warp_m * 64 + mi * 16 + qrow + h * 8;
                const float* lrow = labels + (size_t)grow * N_ROWS + col0 + warp_n * 32;
                float s = 0.f, a = 0.f, b = 0.f;
                #pragma unroll
                for (int ni = 0; ni < 4; ++ni) {
                    const int gcol = col0 + warp_n * 32 + ni * 8 + qcol;
                    float2 lv = __ldcs((const float2*)(lrow + ni * 8 + qcol));
                    float s0 = acc[mi][ni][h * 2 + 0];
                    float s1 = acc[mi][ni][h * 2 + 1];
                    if (gcol != grow) {                  // only binds on diag tiles
                        s += __expf(s0);
                        a = fmaf(lv.x, s0, a);
                        b += lv.x;
                    }
                    if (gcol + 1 != grow) {
                        s += __expf(s1);
                        a = fmaf(lv.y, s1, a);
                        b += lv.y;
                    }
                }
                s += __shfl_xor_sync(0xffffffffu, s, 1);
                s += __shfl_xor_sync(0xffffffffu, s, 2);
                a += __shfl_xor_sync(0xffffffffu, a, 1);
                a += __shfl_xor_sync(0xffffffffu, a, 2);
                b += __shfl_xor_sync(0xffffffffu, b, 1);
                b += __shfl_xor_sync(0xffffffffu, b, 2);
                if ((lane & 3) == 0) {
                    g_ps[stripe * N_ROWS + grow] = s;
                    g_pa[stripe * N_ROWS + grow] = a;
                    g_pb[stripe * N_ROWS + grow] = b;
                }
            }
        }
    }

    // ---- pass 2 (off-diag only): column partials for n-block rows (dir-2) ----
    if (offdiag) {
        const int slot  = tm * 4 + warp_m * 2;
        const int zslot = slot + 1;                 // hole slot: zero-filled here
        #pragma unroll
        for (int ni = 0; ni < 4; ++ni) {
            const int gc0 = col0 + warp_n * 32 + ni * 8 + qcol;   // output rows gc0, gc0+1
            const float* lc0 = labels + (size_t)gc0 * N_ROWS;
            const float* lc1 = lc0 + N_ROWS;
            float s0 = 0.f, s1 = 0.f, a0 = 0.f, a1 = 0.f, b0 = 0.f, b1 = 0.f;
            #pragma unroll
            for (int mi = 0; mi < 4; ++mi) {
                #pragma unroll
                for (int h = 0; h < 2; ++h) {
                    const int grow = row0 + warp_m * 64 + mi * 16 + h * 8 + qrow;
                    float v0 = acc[mi][ni][h * 2 + 0];
                    float v1 = acc[mi][ni][h * 2 + 1];
                    float l0 = __ldcs(lc0 + grow);     // lbl[gc0][grow]
                    float l1 = __ldcs(lc1 + grow);     // lbl[gc0+1][grow]
                    s0 += __expf(v0);
                    s1 += __expf(v1);
                    a0 = fmaf(l0, v0, a0);
                    a1 = fmaf(l1, v1, a1);
                    b0 += l0;
                    b1 += l1;
                }
            }
            #pragma unroll
            for (int o = 4; o <= 16; o <<= 1) {
                s0 += __shfl_xor_sync(0xffffffffu, s0, o);
                s1 += __shfl_xor_sync(0xffffffffu, s1, o);
                a0 += __shfl_xor_sync(0xffffffffu, a0, o);
                a1 += __shfl_xor_sync(0xffffffffu, a1, o);
                b0 += __shfl_xor_sync(0xffffffffu, b0, o);
                b1 += __shfl_xor_sync(0xffffffffu, b1, o);
            }
            if (qrow == 0) {
                g_ps[slot * N_ROWS + gc0]     = s0;
                g_ps[slot * N_ROWS + gc0 + 1] = s1;
                g_pa[slot * N_ROWS + gc0]     = a0;
                g_pa[slot * N_ROWS + gc0 + 1] = a1;
                g_pb[slot * N_ROWS + gc0]     = b0;
                g_pb[slot * N_ROWS + gc0 + 1] = b1;
                // zero-fill the hole slot (replaces the standalone zero kernel)
                g_ps[zslot * N_ROWS + gc0]     = 0.f;
                g_ps[zslot * N_ROWS + gc0 + 1] = 0.f;
                g_pa[zslot * N_ROWS + gc0]     = 0.f;
                g_pa[zslot * N_ROWS + gc0 + 1] = 0.f;
                g_pb[zslot * N_ROWS + gc0]     = 0.f;
                g_pb[zslot * N_ROWS + gc0 + 1] = 0.f;
            }
        }
    }
}

// ------------------------------------------------------------------
// Kernel 3: per-row reduction of the 256 stripe partials + per-CTA loss partial
// 256 CTAs x 256 threads; tid%32 -> row (coalesced), tid/32 -> group of 32 slots.
// ------------------------------------------------------------------
__global__ __launch_bounds__(256) void coref_rowloss_kernel() {
    const int rlane = threadIdx.x & 31;
    const int grp   = threadIdx.x >> 5;            // 0..7
    const int row   = blockIdx.x * 32 + rlane;
    float S = 0.f, A = 0.f, B = 0.f;
    #pragma unroll 8
    for (int k = 0; k < 32; ++k) {
        const int t = grp * 32 + k;
        S += g_ps[t * N_ROWS + row];
        A += g_pa[t * N_ROWS + row];
        B += g_pb[t * N_ROWS + row];
    }
    __shared__ float ss[8][32], sa[8][32], sb2[8][32];
    ss[grp][rlane] = S; sa[grp][rlane] = A; sb2[grp][rlane] = B;
    __syncthreads();
    if (grp == 0) {
        float St = 0.f, At = 0.f, Bt = 0.f;
        #pragma unroll
        for (int g = 0; g < 8; ++g) {
            St += ss[g][rlane]; At += sa[g][rlane]; Bt += sb2[g][rlane];
        }
        // loss_i = lse_i * B_i - A_i   (no max shift: |sim| <= 5)
        float loss = logf(St) * Bt - At;
        // fold the mean partway: fixed-tree reduce over this CTA's 32 rows
        #pragma unroll
        for (int o = 16; o > 0; o >>= 1) loss += __shfl_xor_sync(0xffffffffu, loss, o);
        if (rlane == 0) g_blocksum[blockIdx.x] = loss;
    }
}

// ------------------------------------------------------------------
// Kernel 4: deterministic fixed-tree reduce of 256 block partials -> mean
// ------------------------------------------------------------------
__global__ __launch_bounds__(256) void coref_final_kernel(float* __restrict__ out) {
    __shared__ float sm[256];
    const int t = threadIdx.x;
    sm[t] = g_blocksum[t];
    __syncthreads();
    #pragma unroll
    for (int s = 128; s > 0; s >>= 1) {
        if (t < s) sm[t] += sm[t + s];
        __syncthreads();
    }
    if (t == 0) out[0] = sm[0] * (1.0f / (float)N_ROWS);
}

// ------------------------------------------------------------------
// Launcher (graph-capturable)
// ------------------------------------------------------------------
extern "C" void kernel_launch(void* const* d_in, const int* in_sizes, int n_in,
                              void* d_out, int out_size) {
    const float* embs   = (const float*)d_in[0];
    const float* labels = (const float*)d_in[1];
    if (n_in >= 2 && in_sizes[0] == N_ROWS * N_ROWS) {  // defensive input-order check
        const float* tmp = embs; embs = labels; labels = tmp;
    }
    float* out = (float*)d_out;

    cudaFuncSetAttribute(coref_main_kernel,
                         cudaFuncAttributeMaxDynamicSharedMemorySize, SMEM_BYTES);

    coref_norm_kernel<<<N_ROWS, 256>>>(embs);
    coref_main_kernel<<<NTRI, THREADS, SMEM_BYTES>>>(labels);
    coref_rowloss_kernel<<<NRL_CTAS, 256>>>();
    coref_final_kernel<<<1, 256>>>(out);
}